// round 11
// baseline (speedup 1.0000x reference)
#include <cuda_runtime.h>
#include <math.h>

#define BD 8
#define HD 48
#define WD 48
#define CD 256
#define NPIX (BD * HD * WD)     // 18432
#define PIXB (HD * WD)          // 2304 pixels per batch
#define PLANE (HD * WD)         // 2304 elems per corr plane
#define SPPB   24               // stats pixels per block (6 warps x 4)
#define SBLKPB (PIXB / SPPB)    // 96 stats blocks per batch
#define NSTATS (BD * SBLKPB)    // 768 stats blocks total
#define NAPPLY NPIX             // 18432 apply blocks (1 plane each)

// ---- scratch (device globals; no allocation allowed) ----
__device__ float    g_cvraw[NPIX * 2];
__device__ float    g_partials[NSTATS * 2];  // (sum, sumsq) per stats block
__device__ float    g_stats[BD * 2];         // (mu, inv_std) per batch
__device__ unsigned g_tick[BD];              // stats ticket (self-resetting)
__device__ unsigned g_ready[BD];             // per-batch ready flag (self-resetting)
__device__ unsigned g_adone[BD];             // apply-exit ticket (self-resetting)

// One kernel, two roles by blockIdx.x:
//   bids [0, NSTATS)           : stats producer blocks (192 thr = 6 warps, 4 px/warp)
//   bids [NSTATS, NSTATS+NPIX) : apply consumer blocks (1 corr plane each)
__global__ __launch_bounds__(192) void k_fused(
    const float* __restrict__ x,
    const float* __restrict__ map_w, const float* __restrict__ map_b,
    const float* __restrict__ mean_w, const float* __restrict__ mean_b,
    const float* __restrict__ cov_w, const float* __restrict__ cov_b,
    const float* __restrict__ corr,
    float* __restrict__ out_corr1, float* __restrict__ out_mean,
    float* __restrict__ out_det)
{
    __shared__ float4 sw4[16 * 64];   // map_w as float4 [o][c/4], 16KB (stats only)
    __shared__ float red[SPPB * 2];
    __shared__ float sred[SBLKPB], sqred[SBLKPB];
    __shared__ int   s_last;
    const int tid = threadIdx.x;

    if (blockIdx.x < NSTATS) {
        // ===================== STATS PRODUCER =====================
        {
            const float4* w4 = (const float4*)map_w;
            for (int i = tid; i < 16 * 64; i += 192) sw4[i] = w4[i];
        }
        __syncthreads();

        const int warp = tid >> 5, lane = tid & 31;
        const int batch = blockIdx.x / SBLKPB;
        const int o = lane & 15;
        const int p = lane >> 4;
        const int hl = lane & 15;
        const int q = hl >> 2;
        const float4* __restrict__ x4 = (const float4*)x;

#pragma unroll
        for (int j = 0; j < 2; j++) {
            const int pidA = blockIdx.x * SPPB + warp * 4 + j * 2;  // pixel A (B=A+1)

            const float4 xA0 = x4[(size_t)pidA * 64 + lane];
            const float4 xA1 = x4[(size_t)pidA * 64 + 32 + lane];
            const float4 xB0 = x4[(size_t)(pidA + 1) * 64 + lane];
            const float4 xB1 = x4[(size_t)(pidA + 1) * 64 + 32 + lane];

            float acc[32];
#pragma unroll
            for (int oo = 0; oo < 16; oo++) {
                const float4 w0 = sw4[oo * 64 + lane];
                const float4 w1 = sw4[oo * 64 + 32 + lane];
                float a = xA0.x * w0.x;
                a = fmaf(xA0.y, w0.y, a); a = fmaf(xA0.z, w0.z, a); a = fmaf(xA0.w, w0.w, a);
                a = fmaf(xA1.x, w1.x, a); a = fmaf(xA1.y, w1.y, a);
                a = fmaf(xA1.z, w1.z, a); a = fmaf(xA1.w, w1.w, a);
                float c = xB0.x * w0.x;
                c = fmaf(xB0.y, w0.y, c); c = fmaf(xB0.z, w0.z, c); c = fmaf(xB0.w, w0.w, c);
                c = fmaf(xB1.x, w1.x, c); c = fmaf(xB1.y, w1.y, c);
                c = fmaf(xB1.z, w1.z, c); c = fmaf(xB1.w, w1.w, c);
                acc[oo] = a;
                acc[16 + oo] = c;
            }

            // Multi-value butterfly: lane l ends holding the full sum of acc[l]
#pragma unroll
            for (int d = 16; d >= 1; d >>= 1) {
                const int half = d;
#pragma unroll
                for (int jj = 0; jj < 16; jj++) {
                    if (jj < half) {
                        float send = (lane & d) ? acc[jj] : acc[jj + half];
                        float recv = __shfl_xor_sync(0xffffffffu, send, d);
                        float mine = (lane & d) ? acc[jj + half] : acc[jj];
                        acc[jj] = mine + recv;
                    }
                }
            }
            const float tt = tanhf(acc[0] + __ldg(&map_b[o]));

            float vals[4];
            vals[0] = tt * __ldg(&mean_w[o]);
            vals[1] = tt * __ldg(&mean_w[16 + o]);
            vals[2] = tt * __ldg(&cov_w[o]);
            vals[3] = tt * __ldg(&cov_w[16 + o]);
            {   // d=8: 4->2
                float send = (lane & 8) ? vals[0] : vals[2];
                float recv = __shfl_xor_sync(0xffffffffu, send, 8);
                vals[0] = ((lane & 8) ? vals[2] : vals[0]) + recv;
                send = (lane & 8) ? vals[1] : vals[3];
                recv = __shfl_xor_sync(0xffffffffu, send, 8);
                vals[1] = ((lane & 8) ? vals[3] : vals[1]) + recv;
            }
            {   // d=4: 2->1
                float send = (lane & 4) ? vals[0] : vals[1];
                float recv = __shfl_xor_sync(0xffffffffu, send, 4);
                vals[0] = ((lane & 4) ? vals[1] : vals[0]) + recv;
            }
            vals[0] += __shfl_xor_sync(0xffffffffu, vals[0], 2);
            vals[0] += __shfl_xor_sync(0xffffffffu, vals[0], 1);
            // quad q: q0=m0, q1=m1, q2=c0, q3=c1 (replicated x4)

            const int pid = pidA + p;
            const int hw = pid % PIXB;
            const float r = vals[0];

            if (hl == 0) out_mean[pid * 2 + 0] = (float)(hw % WD) + __ldg(&mean_b[0]) + r;
            if (hl == 4) out_mean[pid * 2 + 1] = (float)(hw / WD) + __ldg(&mean_b[1]) + r;

            const float cb = r + __ldg(&cov_b[q & 1]);
            const float ex = __shfl_xor_sync(0xffffffffu, cb, 4);
            if (hl == 8)  g_cvraw[pid * 2 + 0] = cb;
            if (hl == 12) g_cvraw[pid * 2 + 1] = cb;
            if (hl == 8) {
                red[(warp * 4 + j * 2 + p) * 2 + 0] = cb + ex;
                red[(warp * 4 + j * 2 + p) * 2 + 1] = cb * cb + ex * ex;
            }
        }
        __syncthreads();

        // block partial (fixed order) + ticket
        if (tid == 0) {
            float s = 0.f, qq = 0.f;
#pragma unroll
            for (int i = 0; i < SPPB; i++) { s += red[i * 2]; qq += red[i * 2 + 1]; }
            g_partials[blockIdx.x * 2 + 0] = s;
            g_partials[blockIdx.x * 2 + 1] = qq;
            __threadfence();
            const unsigned prev = atomicAdd(&g_tick[batch], 1u);
            s_last = (prev == SBLKPB - 1);
        }
        __syncthreads();

        // elected last block of this batch: deterministic fixed-order reduction
        if (s_last) {
            __threadfence();
            if (tid < SBLKPB) {
                sred[tid]  = g_partials[(batch * SBLKPB + tid) * 2 + 0];
                sqred[tid] = g_partials[(batch * SBLKPB + tid) * 2 + 1];
            }
            __syncthreads();
            if (tid == 0) {
                float s = 0.f, qq = 0.f;
#pragma unroll
                for (int i = 0; i < SBLKPB; i++) { s += sred[i]; qq += sqred[i]; }
                const float n = (float)(PIXB * 2);     // 4608
                const float mu = s / n;
                const float var = qq / n - mu * mu + 1e-5f;
                g_stats[batch * 2 + 0] = mu;
                g_stats[batch * 2 + 1] = rsqrtf(var);
                g_tick[batch] = 0;                     // reset for next replay
                // release: all batch data (cvraw/mean/stats) visible before flag
                asm volatile("st.release.gpu.global.u32 [%0], %1;"
                             :: "l"(&g_ready[batch]), "r"(1u) : "memory");
            }
        }
        return;
    }

    // ===================== APPLY CONSUMER =====================
    const int pid = blockIdx.x - NSTATS;        // plane index 0..18431
    const int batch = pid / PIXB;
    const int t = tid;
    const float4* __restrict__ src = (const float4*)(corr + (size_t)pid * PLANE);
    float4* __restrict__ dst = (float4*)(out_corr1 + (size_t)pid * PLANE);

    // issue the 3 streaming DRAM loads FIRST — they don't depend on stats and
    // keep HBM busy while we wait for this batch's ready flag
    float4 c[3];
#pragma unroll
    for (int it = 0; it < 3; it++) c[it] = __ldcs(src + t + it * 192);

    // spin on per-batch ready flag (acquire), loads above already in flight
    if (t == 0) {
        unsigned r;
        do {
            asm volatile("ld.acquire.gpu.global.u32 %0, [%1];"
                         : "=r"(r) : "l"(&g_ready[batch]) : "memory");
            if (!r) __nanosleep(128);
        } while (!r);
    }
    __syncthreads();

    // per-pixel params (broadcast loads, L2-hit; ordered after flag by syncthreads)
    const float mu = g_stats[batch * 2 + 0], istd = g_stats[batch * 2 + 1];
    float c0 = (g_cvraw[pid * 2 + 0] - mu) * istd;
    float c1 = (g_cvraw[pid * 2 + 1] - mu) * istd;
    c0 = 5.f / (1.f + __expf(-c0)) + 0.05f;
    c1 = 5.f / (1.f + __expf(-c1)) + 0.05f;
    const float det = c0 * c1;
    if (t == 0) out_det[pid] = det;
    const float mx = __ldg(&out_mean[pid * 2 + 0]);
    const float my = __ldg(&out_mean[pid * 2 + 1]);
    const float ax = -0.5f / c0;
    const float ay = -0.5f / c1;
    const float s = rsqrtf(det) * (1.0f / 6.28f);

#pragma unroll
    for (int it = 0; it < 3; it++) {
        const int i = t + it * 192;          // float4 index in plane (0..575)
        const int h2 = i / 12;               // 12 float4s per 48-float row
        const float dy = (float)h2 - my;
        const bool iny = fabsf(dy) <= 6.0f;
        const float qy = ay * dy * dy;
        const float dx0 = (float)((i % 12) * 4) - mx;
        float4 v = c[it];
        {
            const float dx = dx0 + 0.f;
            if (iny && fabsf(dx) <= 6.0f)
                v.x = fmaf(v.x * s, __expf(fmaf(ax, dx * dx, qy)), v.x);
        }
        {
            const float dx = dx0 + 1.f;
            if (iny && fabsf(dx) <= 6.0f)
                v.y = fmaf(v.y * s, __expf(fmaf(ax, dx * dx, qy)), v.y);
        }
        {
            const float dx = dx0 + 2.f;
            if (iny && fabsf(dx) <= 6.0f)
                v.z = fmaf(v.z * s, __expf(fmaf(ax, dx * dx, qy)), v.z);
        }
        {
            const float dx = dx0 + 3.f;
            if (iny && fabsf(dx) <= 6.0f)
                v.w = fmaf(v.w * s, __expf(fmaf(ax, dx * dx, qy)), v.w);
        }
        __stcs(dst + i, v);
    }

    // exit ticket: last apply block of this batch resets flags for next replay
    if (t == 0) {
        __threadfence();
        const unsigned prev = atomicAdd(&g_adone[batch], 1u);
        if (prev == (unsigned)(PIXB - 1)) {
            g_ready[batch] = 0u;
            g_adone[batch] = 0u;
        }
    }
}

// ======================================================================
extern "C" void kernel_launch(void* const* d_in, const int* in_sizes, int n_in,
                              void* d_out, int out_size)
{
    const float* x      = (const float*)d_in[0];
    const float* corr   = (const float*)d_in[1];
    const float* map_w  = (const float*)d_in[2];
    const float* map_b  = (const float*)d_in[3];
    const float* mean_w = (const float*)d_in[4];
    const float* mean_b = (const float*)d_in[5];
    const float* cov_w  = (const float*)d_in[6];
    const float* cov_b  = (const float*)d_in[7];

    float* out = (float*)d_out;
    // outputs concatenated flat: corr1 (b,h,w,h,w), mean (b,h,w,2), det (b,h*w)
    float* out_corr1 = out;
    float* out_mean  = out + (size_t)NPIX * PLANE;
    float* out_det   = out_mean + (size_t)NPIX * 2;

    k_fused<<<NSTATS + NAPPLY, 192>>>(x, map_w, map_b, mean_w, mean_b,
                                      cov_w, cov_b, corr,
                                      out_corr1, out_mean, out_det);
}

// round 12
// speedup vs baseline: 1.4292x; 1.4292x over previous
#include <cuda_runtime.h>
#include <math.h>

#define BD 8
#define HD 48
#define WD 48
#define CD 256
#define NPIX (BD * HD * WD)     // 18432
#define PIXB (HD * WD)          // 2304 pixels per batch
#define PLANE (HD * WD)         // 2304 elems per corr plane
#define SPPB   32               // stats pixels per block (8 warps x 4)
#define SBLKPB (PIXB / SPPB)    // 72 stats blocks per batch
#define NSTATS (BD * SBLKPB)    // 576 stats blocks total

// ---- scratch (device globals; no allocation allowed) ----
__device__ float    g_cvraw[NPIX * 2];
__device__ float    g_partials[NSTATS * 2];  // (sum, sumsq) per stats block
__device__ float    g_stats[BD * 2];         // (mu, inv_std) per batch
__device__ unsigned g_tick[BD];              // stats ticket (self-resetting)

// ================= Kernel 1: MLP + mean + cvraw + fused per-batch reduction =========
// 8 warps x 4 pixels/warp. Weight loads hoisted: one w0/w1 pair per output index
// feeds all 4 pixels -> smem crossbar traffic per pixel halved vs round 8/10.
__global__ __launch_bounds__(256) void k_stats(
    const float* __restrict__ x,
    const float* __restrict__ map_w, const float* __restrict__ map_b,
    const float* __restrict__ mean_w, const float* __restrict__ mean_b,
    const float* __restrict__ cov_w, const float* __restrict__ cov_b,
    float* __restrict__ out_mean)
{
    __shared__ float4 sw4[16 * 64];   // map_w as float4 [o][c/4], 16KB
    __shared__ float red[SPPB * 2];   // per-pixel (sum, sumsq)
    __shared__ float sred[SBLKPB], sqred[SBLKPB];
    __shared__ int   s_last;
    const int tid = threadIdx.x;
    {
        const float4* w4 = (const float4*)map_w;
        for (int i = tid; i < 16 * 64; i += 256) sw4[i] = w4[i];
    }
    __syncthreads();

    const int warp = tid >> 5, lane = tid & 31;
    const int batch = blockIdx.x / SBLKPB;
    const int o = lane & 15;
    const int p = lane >> 4;
    const int hl = lane & 15;
    const int q = hl >> 2;
    const float4* __restrict__ x4 = (const float4*)x;

    const int pidA = blockIdx.x * SPPB + warp * 4;   // pixels A,B,C,D = pidA..pidA+3

    const float4 xA0 = x4[(size_t)pidA * 64 + lane];
    const float4 xA1 = x4[(size_t)pidA * 64 + 32 + lane];
    const float4 xB0 = x4[(size_t)(pidA + 1) * 64 + lane];
    const float4 xB1 = x4[(size_t)(pidA + 1) * 64 + 32 + lane];
    const float4 xC0 = x4[(size_t)(pidA + 2) * 64 + lane];
    const float4 xC1 = x4[(size_t)(pidA + 2) * 64 + 32 + lane];
    const float4 xD0 = x4[(size_t)(pidA + 3) * 64 + lane];
    const float4 xD1 = x4[(size_t)(pidA + 3) * 64 + 32 + lane];

    float accP[32], accQ[32];   // pair {A,B} and pair {C,D}
#pragma unroll
    for (int oo = 0; oo < 16; oo++) {
        const float4 w0 = sw4[oo * 64 + lane];
        const float4 w1 = sw4[oo * 64 + 32 + lane];
        float a = xA0.x * w0.x;
        a = fmaf(xA0.y, w0.y, a); a = fmaf(xA0.z, w0.z, a); a = fmaf(xA0.w, w0.w, a);
        a = fmaf(xA1.x, w1.x, a); a = fmaf(xA1.y, w1.y, a);
        a = fmaf(xA1.z, w1.z, a); a = fmaf(xA1.w, w1.w, a);
        float b = xB0.x * w0.x;
        b = fmaf(xB0.y, w0.y, b); b = fmaf(xB0.z, w0.z, b); b = fmaf(xB0.w, w0.w, b);
        b = fmaf(xB1.x, w1.x, b); b = fmaf(xB1.y, w1.y, b);
        b = fmaf(xB1.z, w1.z, b); b = fmaf(xB1.w, w1.w, b);
        float c = xC0.x * w0.x;
        c = fmaf(xC0.y, w0.y, c); c = fmaf(xC0.z, w0.z, c); c = fmaf(xC0.w, w0.w, c);
        c = fmaf(xC1.x, w1.x, c); c = fmaf(xC1.y, w1.y, c);
        c = fmaf(xC1.z, w1.z, c); c = fmaf(xC1.w, w1.w, c);
        float d = xD0.x * w0.x;
        d = fmaf(xD0.y, w0.y, d); d = fmaf(xD0.z, w0.z, d); d = fmaf(xD0.w, w0.w, d);
        d = fmaf(xD1.x, w1.x, d); d = fmaf(xD1.y, w1.y, d);
        d = fmaf(xD1.z, w1.z, d); d = fmaf(xD1.w, w1.w, d);
        accP[oo] = a;  accP[16 + oo] = b;
        accQ[oo] = c;  accQ[16 + oo] = d;
    }

    // Two multi-value butterflies: lane l ends holding full sums of accP[l], accQ[l]
#pragma unroll
    for (int d = 16; d >= 1; d >>= 1) {
        const int half = d;
#pragma unroll
        for (int jj = 0; jj < 16; jj++) {
            if (jj < half) {
                {
                    float send = (lane & d) ? accP[jj] : accP[jj + half];
                    float recv = __shfl_xor_sync(0xffffffffu, send, d);
                    float mine = (lane & d) ? accP[jj + half] : accP[jj];
                    accP[jj] = mine + recv;
                }
                {
                    float send = (lane & d) ? accQ[jj] : accQ[jj + half];
                    float recv = __shfl_xor_sync(0xffffffffu, send, d);
                    float mine = (lane & d) ? accQ[jj + half] : accQ[jj];
                    accQ[jj] = mine + recv;
                }
            }
        }
    }

    const float mbo = __ldg(&map_b[o]);
    const float mw0 = __ldg(&mean_w[o]),      mw1 = __ldg(&mean_w[16 + o]);
    const float cw0 = __ldg(&cov_w[o]),       cw1 = __ldg(&cov_w[16 + o]);

#pragma unroll
    for (int j = 0; j < 2; j++) {
        const float tt = tanhf((j == 0 ? accP[0] : accQ[0]) + mbo);

        float vals[4];
        vals[0] = tt * mw0;
        vals[1] = tt * mw1;
        vals[2] = tt * cw0;
        vals[3] = tt * cw1;
        {   // d=8: 4->2
            float send = (lane & 8) ? vals[0] : vals[2];
            float recv = __shfl_xor_sync(0xffffffffu, send, 8);
            vals[0] = ((lane & 8) ? vals[2] : vals[0]) + recv;
            send = (lane & 8) ? vals[1] : vals[3];
            recv = __shfl_xor_sync(0xffffffffu, send, 8);
            vals[1] = ((lane & 8) ? vals[3] : vals[1]) + recv;
        }
        {   // d=4: 2->1
            float send = (lane & 4) ? vals[0] : vals[1];
            float recv = __shfl_xor_sync(0xffffffffu, send, 4);
            vals[0] = ((lane & 4) ? vals[1] : vals[0]) + recv;
        }
        vals[0] += __shfl_xor_sync(0xffffffffu, vals[0], 2);
        vals[0] += __shfl_xor_sync(0xffffffffu, vals[0], 1);
        // quad q: q0=m0, q1=m1, q2=c0, q3=c1 (replicated x4)

        const int pid = pidA + j * 2 + p;
        const int hw = pid % PIXB;
        const float r = vals[0];

        if (hl == 0) out_mean[pid * 2 + 0] = (float)(hw % WD) + __ldg(&mean_b[0]) + r;
        if (hl == 4) out_mean[pid * 2 + 1] = (float)(hw / WD) + __ldg(&mean_b[1]) + r;

        const float cb = r + __ldg(&cov_b[q & 1]);
        const float ex = __shfl_xor_sync(0xffffffffu, cb, 4);
        if (hl == 8)  g_cvraw[pid * 2 + 0] = cb;
        if (hl == 12) g_cvraw[pid * 2 + 1] = cb;
        if (hl == 8) {
            red[(warp * 4 + j * 2 + p) * 2 + 0] = cb + ex;
            red[(warp * 4 + j * 2 + p) * 2 + 1] = cb * cb + ex * ex;
        }
    }
    __syncthreads();

    // block partial (fixed order) + ticket
    if (tid == 0) {
        float s = 0.f, qq = 0.f;
#pragma unroll
        for (int i = 0; i < SPPB; i++) { s += red[i * 2]; qq += red[i * 2 + 1]; }
        g_partials[blockIdx.x * 2 + 0] = s;
        g_partials[blockIdx.x * 2 + 1] = qq;
        __threadfence();
        const unsigned prev = atomicAdd(&g_tick[batch], 1u);
        s_last = (prev == SBLKPB - 1);
    }
    __syncthreads();

    // elected last block of this batch: deterministic fixed-order reduction
    if (s_last) {
        __threadfence();
        if (tid < SBLKPB) {
            sred[tid]  = g_partials[(batch * SBLKPB + tid) * 2 + 0];
            sqred[tid] = g_partials[(batch * SBLKPB + tid) * 2 + 1];
        }
        __syncthreads();
        if (tid == 0) {
            float s = 0.f, qq = 0.f;
#pragma unroll
            for (int i = 0; i < SBLKPB; i++) { s += sred[i]; qq += sqred[i]; }
            const float n = (float)(PIXB * 2);     // 4608
            const float mu = s / n;
            const float var = qq / n - mu * mu + 1e-5f;
            g_stats[batch * 2 + 0] = mu;
            g_stats[batch * 2 + 1] = rsqrtf(var);
            g_tick[batch] = 0;                     // reset for next graph replay
        }
    }
}

// ================= Kernel 2: HBM-bound apply (round-8 shape: regs 30, occ 82%) =====
__global__ __launch_bounds__(192) void k_apply(
    const float* __restrict__ corr, float* __restrict__ out,
    const float* __restrict__ mean_arr, float* __restrict__ out_det)
{
    const int pid = blockIdx.x;
    const int t = threadIdx.x;
    const float4* __restrict__ src = (const float4*)(corr + (size_t)pid * PLANE);
    float4* __restrict__ dst = (float4*)(out + (size_t)pid * PLANE);

    // issue the 3 streaming DRAM loads first (MLP=3), overlap with param math
    float4 c[3];
#pragma unroll
    for (int it = 0; it < 3; it++) c[it] = __ldcs(src + t + it * 192);

    // per-pixel params (redundant per thread; same-address broadcast, L2-hit)
    const int b = pid / PIXB;
    const float mu = g_stats[b * 2 + 0], istd = g_stats[b * 2 + 1];
    float c0 = (g_cvraw[pid * 2 + 0] - mu) * istd;
    float c1 = (g_cvraw[pid * 2 + 1] - mu) * istd;
    c0 = 5.f / (1.f + __expf(-c0)) + 0.05f;
    c1 = 5.f / (1.f + __expf(-c1)) + 0.05f;
    const float det = c0 * c1;
    if (t == 0) out_det[pid] = det;
    const float mx = __ldg(&mean_arr[pid * 2 + 0]);
    const float my = __ldg(&mean_arr[pid * 2 + 1]);
    const float ax = -0.5f / c0;
    const float ay = -0.5f / c1;
    const float s = rsqrtf(det) * (1.0f / 6.28f);

#pragma unroll
    for (int it = 0; it < 3; it++) {
        const int i = t + it * 192;          // float4 index in plane (0..575)
        const int h2 = i / 12;               // 12 float4s per 48-float row
        const float dy = (float)h2 - my;
        const bool iny = fabsf(dy) <= 6.0f;
        const float qy = ay * dy * dy;
        const float dx0 = (float)((i % 12) * 4) - mx;
        float4 v = c[it];
        {
            const float dx = dx0 + 0.f;
            if (iny && fabsf(dx) <= 6.0f)
                v.x = fmaf(v.x * s, __expf(fmaf(ax, dx * dx, qy)), v.x);
        }
        {
            const float dx = dx0 + 1.f;
            if (iny && fabsf(dx) <= 6.0f)
                v.y = fmaf(v.y * s, __expf(fmaf(ax, dx * dx, qy)), v.y);
        }
        {
            const float dx = dx0 + 2.f;
            if (iny && fabsf(dx) <= 6.0f)
                v.z = fmaf(v.z * s, __expf(fmaf(ax, dx * dx, qy)), v.z);
        }
        {
            const float dx = dx0 + 3.f;
            if (iny && fabsf(dx) <= 6.0f)
                v.w = fmaf(v.w * s, __expf(fmaf(ax, dx * dx, qy)), v.w);
        }
        __stcs(dst + i, v);
    }
}

// ======================================================================
extern "C" void kernel_launch(void* const* d_in, const int* in_sizes, int n_in,
                              void* d_out, int out_size)
{
    const float* x      = (const float*)d_in[0];
    const float* corr   = (const float*)d_in[1];
    const float* map_w  = (const float*)d_in[2];
    const float* map_b  = (const float*)d_in[3];
    const float* mean_w = (const float*)d_in[4];
    const float* mean_b = (const float*)d_in[5];
    const float* cov_w  = (const float*)d_in[6];
    const float* cov_b  = (const float*)d_in[7];

    float* out = (float*)d_out;
    // outputs concatenated flat: corr1 (b,h,w,h,w), mean (b,h,w,2), det (b,h*w)
    float* out_corr1 = out;
    float* out_mean  = out + (size_t)NPIX * PLANE;
    float* out_det   = out_mean + (size_t)NPIX * 2;

    k_stats<<<NSTATS, 256>>>(x, map_w, map_b, mean_w, mean_b, cov_w, cov_b, out_mean);
    k_apply<<<NPIX, 192>>>(corr, out_corr1, out_mean, out_det);
}